// round 11
// baseline (speedup 1.0000x reference)
#include <cuda_runtime.h>
#include <cuda_fp16.h>
#include <math.h>
#include <stdint.h>

#define TSEQ 512
#define KDIM 512
#define VOCAB 32000
#define BT 2048

// ---------- scratch pools (halves) ----------
constexpr long E_H = 2048L*512, E_QKV = 2048L*4096, E_ATT = 32L*512*512,
               E_FF = 2048L*2048, E_W3 = 4L*4096*512, E_W12 = 4L*2048*512,
               E_UN = 32000L*512;
// A-side tensors keep hi+lo planes; B-side (weights, K, V^T) single plane.
constexpr long O_HHI=0, O_HLO=O_HHI+E_H,
 O_QHI=O_HLO+E_H, O_QLO=O_QHI+E_QKV,
 O_K  =O_QLO+E_QKV,
 O_VT =O_K  +E_QKV,
 O_ATHI=O_VT+E_ATT, O_ATLO=O_ATHI+E_ATT,
 O_YHI=O_ATLO+E_ATT, O_YLO=O_YHI+E_QKV,
 O_FHI=O_YLO+E_QKV, O_FLO=O_FHI+E_FF,
 O_WQ=O_FLO+E_FF, O_WK=O_WQ+E_W3, O_WV=O_WK+E_W3, O_WU=O_WV+E_W3,
 O_W1=O_WU+E_W3, O_W2=O_W1+E_W12,
 O_UN=O_W2+E_W12, HF_TOTAL=O_UN+E_UN;
__device__ __half g_hf[HF_TOTAL];

constexpr long F_H=0, F_V=F_H+E_H, F_ATT=F_V+E_QKV, F_T1=F_ATT+E_ATT,
               F_TOTAL=F_T1+E_H;
__device__ float g_f[F_TOTAL];

// ---------- helpers ----------
__device__ __forceinline__ uint32_t s2u(const void* p) {
    uint32_t a;
    asm("{ .reg .u64 t; cvta.to.shared.u64 t, %1; cvt.u32.u64 %0, t; }" : "=r"(a) : "l"(p));
    return a;
}
__device__ __forceinline__ void ldm4(uint32_t& r0, uint32_t& r1, uint32_t& r2, uint32_t& r3,
                                     uint32_t addr) {
    asm volatile("ldmatrix.sync.aligned.m8n8.x4.shared.b16 {%0,%1,%2,%3}, [%4];"
                 : "=r"(r0), "=r"(r1), "=r"(r2), "=r"(r3) : "r"(addr));
}
__device__ __forceinline__ void mma16816(float* c, uint32_t a0, uint32_t a1, uint32_t a2,
                                         uint32_t a3, uint32_t b0, uint32_t b1) {
    asm volatile(
        "mma.sync.aligned.m16n8k16.row.col.f32.f16.f16.f32 "
        "{%0,%1,%2,%3}, {%4,%5,%6,%7}, {%8,%9}, {%0,%1,%2,%3};"
        : "+f"(c[0]), "+f"(c[1]), "+f"(c[2]), "+f"(c[3])
        : "r"(a0), "r"(a1), "r"(a2), "r"(a3), "r"(b0), "r"(b1));
}
__device__ __forceinline__ void cpa16(uint32_t dst, const void* src) {
    asm volatile("cp.async.cg.shared.global [%0], [%1], 16;" :: "r"(dst), "l"(src));
}
__device__ __forceinline__ void cpcommit() { asm volatile("cp.async.commit_group;"); }
__device__ __forceinline__ void cpwait0() { asm volatile("cp.async.wait_group 0;"); }
__device__ __forceinline__ void cpwait1() { asm volatile("cp.async.wait_group 1;"); }

__device__ __forceinline__ float gelu_exact(float x) {
    return 0.5f * x * (1.0f + erff(x * 0.70710678118654752f));
}
__device__ __forceinline__ void split_h(float v, __half* hp, __half* lp) {
    __half h = __float2half_rn(v);
    *hp = h; *lp = __float2half_rn(v - __half2float(h));
}
__device__ __forceinline__ uint32_t packh(float a, float b) {
    __half2 t = __floats2half2_rn(a, b);
    return *(uint32_t*)&t;
}
__device__ __forceinline__ float wSum(float v) {
    #pragma unroll
    for (int o = 16; o > 0; o >>= 1) v += __shfl_xor_sync(~0u, v, o);
    return v;
}
__device__ __forceinline__ float wMax(float v) {
    #pragma unroll
    for (int o = 16; o > 0; o >>= 1) v = fmaxf(v, __shfl_xor_sync(~0u, v, o));
    return v;
}

// ---------- fp16 A-split 2-term HMMA GEMM: C[M,N] = alpha*A[M,K]*B[N,K]^T ----------
// Tile: (WM*64) x 128, 8 warps. WM=2: warp 64x32. WM=1: warp 64x16.
// A: hi+lo planes; B: single plane. K-chunk 32, cp.async 2-stage, 80B rows.
// OUT: 0 = fp32, 1 = split hi/lo halves, 2 = single half.
constexpr int ROWB = 80;

template<int WM, int OUT, bool BIAS, bool GELU, int CAUSAL>
__global__ void __launch_bounds__(256, 2)
tc_gemm(const __half* __restrict__ Ah, const __half* __restrict__ Al,
        int lda, long sAb, long sAh,
        const __half* __restrict__ Bh,
        int ldb, long sBb, long sBh,
        const float* __restrict__ bias,
        float* __restrict__ Cf, __half* __restrict__ Chi, __half* __restrict__ Clo,
        int ldc, long sCb, long sCh, int Kd, int Hdiv, float alpha)
{
    constexpr int MT  = WM * 64;
    constexpr int WNW = 8 / WM;
    constexpr int NW  = 128 / WNW;
    constexpr int NFR = NW / 8;
    constexpr int APL = MT * ROWB;
    constexpr int BPL = 128 * ROWB;
    constexpr int STGB = 2 * APL + BPL;

    const int m0 = blockIdx.y * MT, n0 = blockIdx.x * 128;
    if (CAUSAL == 1 && n0 > m0 + MT - 1) return;

    const int bz = blockIdx.z, bb = bz / Hdiv, hh = bz - bb * Hdiv;
    Ah += (long)bb*sAb + (long)hh*sAh;  Al += (long)bb*sAb + (long)hh*sAh;
    Bh += (long)bb*sBb + (long)hh*sBh;
    const long coff = (long)bb*sCb + (long)hh*sCh;

    extern __shared__ char smem[];
    const uint32_t sb = s2u(smem);
    const int tid = threadIdx.x, wid = tid >> 5, lane = tid & 31;
    const int wm = wid / WNW, wn = wid % WNW;

    int nk = Kd >> 5;
    if (CAUSAL == 2) { int kl = m0 + MT; if (kl > Kd) kl = Kd; nk = kl >> 5; }

    float acc[4][NFR][4];
    #pragma unroll
    for (int i = 0; i < 4; i++)
        #pragma unroll
        for (int j = 0; j < NFR; j++)
            #pragma unroll
            for (int q = 0; q < 4; q++) acc[i][j][q] = 0.0f;

    auto load_stage = [&](int st, int kt) {
        const int k0 = kt << 5;
        const uint32_t base = sb + st * STGB;
        // A: 2 planes x MT rows x 4 chunks of 16B
        #pragma unroll
        for (int it = 0; it < MT / 32; it++) {
            int id = it * 256 + tid;
            int plane = id / (MT * 4), rem = id % (MT * 4), r = rem >> 2, c = rem & 3;
            const __half* src = plane ? Al : Ah;
            cpa16(base + plane * APL + r * ROWB + c * 16,
                  src + (long)(m0 + r) * lda + k0 + c * 8);
        }
        // B: 1 plane x 128 rows x 4 chunks
        #pragma unroll
        for (int it = 0; it < 2; it++) {
            int id = it * 256 + tid;
            int r = id >> 2, c = id & 3;
            cpa16(base + 2 * APL + r * ROWB + c * 16,
                  Bh + (long)(n0 + r) * ldb + k0 + c * 8);
        }
    };

    load_stage(0, 0);
    cpcommit();

    for (int kt = 0; kt < nk; kt++) {
        const int st = kt & 1;
        if (kt + 1 < nk) { load_stage(st ^ 1, kt + 1); cpcommit(); cpwait1(); }
        else cpwait0();
        __syncthreads();

        const uint32_t stg = sb + st * STGB;
        #pragma unroll
        for (int kk = 0; kk < 2; kk++) {
            // B fragments (single plane, hoisted)
            uint32_t bh[NFR][2];
            {
                const int q = lane >> 3, w8 = lane & 7;
                const uint32_t rofs = (uint32_t)(wn * NW + w8 + ((q >> 1) << 3)) * ROWB
                                    + kk * 32 + ((q & 1) << 4);
                #pragma unroll
                for (int np = 0; np < NFR / 2; np++) {
                    uint32_t bd = stg + 2 * APL + rofs + (uint32_t)(np * 16) * ROWB;
                    uint32_t r0, r1, r2, r3;
                    ldm4(r0, r1, r2, r3, bd);
                    bh[np*2][0] = r0; bh[np*2][1] = r1;
                    bh[np*2+1][0] = r2; bh[np*2+1][1] = r3;
                }
            }
            // A per-mf: hi + lo, 2-term MMA
            const uint32_t rofsA = (uint32_t)(wm * 64 + (lane & 15)) * ROWB
                                 + kk * 32 + ((lane >> 4) << 4);
            #pragma unroll
            for (int mf = 0; mf < 4; mf++) {
                uint32_t a0, a1, a2, a3, l0, l1, l2, l3;
                uint32_t ad = stg + rofsA + (uint32_t)(mf * 16) * ROWB;
                ldm4(a0, a1, a2, a3, ad);
                ldm4(l0, l1, l2, l3, ad + APL);
                #pragma unroll
                for (int nf = 0; nf < NFR; nf++) {
                    mma16816(acc[mf][nf], a0, a1, a2, a3, bh[nf][0], bh[nf][1]);
                    mma16816(acc[mf][nf], l0, l1, l2, l3, bh[nf][0], bh[nf][1]);
                }
            }
        }
        __syncthreads();
    }

    // ---- epilogue ----
    const int mbase = m0 + wm * 64 + (lane >> 2);
    const int nbase = n0 + wn * NW + (lane & 3) * 2;
    #pragma unroll
    for (int mf = 0; mf < 4; mf++) {
        #pragma unroll
        for (int nf = 0; nf < NFR; nf++) {
            const int m = mbase + mf * 16, n = nbase + nf * 8;
            float v0 = acc[mf][nf][0] * alpha, v1 = acc[mf][nf][1] * alpha;
            float v2 = acc[mf][nf][2] * alpha, v3 = acc[mf][nf][3] * alpha;
            if (BIAS) {
                float bb0 = bias[n], bb1 = bias[n + 1];
                v0 += bb0; v1 += bb1; v2 += bb0; v3 += bb1;
            }
            if (GELU) {
                v0 = gelu_exact(v0); v1 = gelu_exact(v1);
                v2 = gelu_exact(v2); v3 = gelu_exact(v3);
            }
            const long r0 = coff + (long)m * ldc + n;
            const long r1 = coff + (long)(m + 8) * ldc + n;
            if (OUT == 0) {
                *(float2*)(Cf + r0) = make_float2(v0, v1);
                *(float2*)(Cf + r1) = make_float2(v2, v3);
            } else if (OUT == 2) {
                *(uint32_t*)(Chi + r0) = packh(v0, v1);
                *(uint32_t*)(Chi + r1) = packh(v2, v3);
            } else {
                __half h0 = __float2half_rn(v0), h1 = __float2half_rn(v1);
                __half h2 = __float2half_rn(v2), h3 = __float2half_rn(v3);
                *(uint32_t*)(Chi + r0) = (uint32_t)*(uint16_t*)&h0 | ((uint32_t)*(uint16_t*)&h1 << 16);
                *(uint32_t*)(Chi + r1) = (uint32_t)*(uint16_t*)&h2 | ((uint32_t)*(uint16_t*)&h3 << 16);
                *(uint32_t*)(Clo + r0) = packh(v0 - __half2float(h0), v1 - __half2float(h1));
                *(uint32_t*)(Clo + r1) = packh(v2 - __half2float(h2), v3 - __half2float(h3));
            }
        }
    }
}

constexpr int SMEM_WM2 = 2 * (2 * 128 * ROWB + 128 * ROWB);  // 61440
constexpr int SMEM_WM1 = 2 * (2 * 64 * ROWB + 128 * ROWB);   // 40960

// ---------- transpose to single fp16: out[C,R] = fp16(in[R,C]) ----------
__global__ void tsplit_ker(const float* __restrict__ in, int ldin, long sInB, long sInH,
                           __half* __restrict__ oh,
                           int ldout, long sOutB, long sOutH, int Hdiv)
{
    __shared__ float t[32][33];
    const int bz = blockIdx.z, bb = bz / Hdiv, hh = bz - bb * Hdiv;
    in += (long)bb*sInB + (long)hh*sInH;
    oh += (long)bb*sOutB + (long)hh*sOutH;
    const int c0 = blockIdx.x * 32, r0 = blockIdx.y * 32;
    const int tx = threadIdx.x, ty = threadIdx.y;
    #pragma unroll
    for (int i = 0; i < 4; i++) {
        int r = ty + i * 8;
        t[r][tx] = in[(long)(r0 + r) * ldin + c0 + tx];
    }
    __syncthreads();
    #pragma unroll
    for (int i = 0; i < 4; i++) {
        int rr = ty + i * 8;
        oh[(long)(c0 + rr) * ldout + r0 + tx] = __float2half_rn(t[tx][rr]);
    }
}

// ---------- embed + positional ----------
__global__ void embed_ker(const int* __restrict__ x, const float* __restrict__ eW,
                          float* __restrict__ h,
                          __half* __restrict__ hh, __half* __restrict__ hl)
{
    long i = (long)blockIdx.x * blockDim.x + threadIdx.x;
    int d = (int)(i & 511);
    long bt = i >> 9;
    int t = (int)(bt & 511);
    int tok = x[bt];
    int j = d >> 1;
    float div = powf(10000.0f, (float)j * (1.0f / 128.0f));
    float ang = (float)t / div;
    float p = (d & 1) ? cosf(ang) : sinf(ang);
    float v = eW[(long)tok * 512 + d] + p;
    h[i] = v;
    split_h(v, hh + i, hl + i);
}

// ---------- causal softmax -> split halves ----------
__global__ void __launch_bounds__(256)
softmax_ker(const float* __restrict__ att,
            __half* __restrict__ oh, __half* __restrict__ ol)
{
    __shared__ float red[8];
    const int r = blockIdx.x, q = r & 511, tid = threadIdx.x;
    const float* row = att + (long)r * 512;
    float x0 = (tid       <= q) ? row[tid]       : -3.0e38f;
    float x1 = (tid + 256 <= q) ? row[tid + 256] : -3.0e38f;
    float m = wMax(fmaxf(x0, x1));
    if ((tid & 31) == 0) red[tid >> 5] = m;
    __syncthreads();
    m = red[0];
    #pragma unroll
    for (int i = 1; i < 8; i++) m = fmaxf(m, red[i]);
    __syncthreads();
    float e0 = (tid       <= q) ? expf(x0 - m) : 0.0f;
    float e1 = (tid + 256 <= q) ? expf(x1 - m) : 0.0f;
    float s = wSum(e0 + e1);
    if ((tid & 31) == 0) red[tid >> 5] = s;
    __syncthreads();
    s = red[0];
    #pragma unroll
    for (int i = 1; i < 8; i++) s += red[i];
    float inv = 1.0f / s;
    long base = (long)r * 512;
    split_h(e0 * inv, oh + base + tid,       ol + base + tid);
    split_h(e1 * inv, oh + base + tid + 256, ol + base + tid + 256);
}

// ---------- (residual+) LayerNorm -> fp32 + split halves ----------
__global__ void __launch_bounds__(256)
ln_ker(const float* __restrict__ in, const float* __restrict__ res,
       const float* __restrict__ w, const float* __restrict__ b,
       float* __restrict__ out, __half* __restrict__ oh, __half* __restrict__ ol)
{
    __shared__ float red[8];
    const int r = blockIdx.x, tid = threadIdx.x;
    const long base = (long)r * 512;
    float x0 = in[base + tid], x1 = in[base + tid + 256];
    if (res) { x0 += res[base + tid]; x1 += res[base + tid + 256]; }
    float s = wSum(x0 + x1);
    if ((tid & 31) == 0) red[tid >> 5] = s;
    __syncthreads();
    float tot = red[0];
    #pragma unroll
    for (int i = 1; i < 8; i++) tot += red[i];
    float mean = tot * (1.0f / 512.0f);
    __syncthreads();
    float d0 = x0 - mean, d1 = x1 - mean;
    float s2 = wSum(d0 * d0 + d1 * d1);
    if ((tid & 31) == 0) red[tid >> 5] = s2;
    __syncthreads();
    float v = red[0];
    #pragma unroll
    for (int i = 1; i < 8; i++) v += red[i];
    float inv = 1.0f / sqrtf(v * (1.0f / 512.0f) + 1e-5f);
    float y0 = d0 * inv * w[tid]       + b[tid];
    float y1 = d1 * inv * w[tid + 256] + b[tid + 256];
    out[base + tid] = y0; out[base + tid + 256] = y1;
    split_h(y0, oh + base + tid,       ol + base + tid);
    split_h(y1, oh + base + tid + 256, ol + base + tid + 256);
}

// ---------- launch ----------
extern "C" void kernel_launch(void* const* d_in, const int* in_sizes, int n_in,
                              void* d_out, int out_size)
{
    (void)in_sizes; (void)n_in; (void)out_size;
    const int*   x    = (const int*)  d_in[0];
    const float* eW   = (const float*)d_in[1];
    const float* Wq   = (const float*)d_in[2];
    const float* Wk   = (const float*)d_in[3];
    const float* Wv   = (const float*)d_in[4];
    const float* Wu   = (const float*)d_in[5];
    const float* bu   = (const float*)d_in[6];
    const float* W1   = (const float*)d_in[7];
    const float* b1   = (const float*)d_in[8];
    const float* W2   = (const float*)d_in[9];
    const float* b2   = (const float*)d_in[10];
    const float* ln1w = (const float*)d_in[11];
    const float* ln1b = (const float*)d_in[12];
    const float* ln2w = (const float*)d_in[13];
    const float* ln2b = (const float*)d_in[14];
    const float* lnfw = (const float*)d_in[15];
    const float* lnfb = (const float*)d_in[16];
    const float* uW   = (const float*)d_in[17];
    const float* ub   = (const float*)d_in[18];
    float* outp = (float*)d_out;

    void *ph = nullptr, *pf = nullptr;
    cudaGetSymbolAddress(&ph, g_hf);
    cudaGetSymbolAddress(&pf, g_f);
    __half* Hp = (__half*)ph;
    float* F = (float*)pf;

    cudaFuncSetAttribute(tc_gemm<2,1,false,false,0>, cudaFuncAttributeMaxDynamicSharedMemorySize, SMEM_WM2);
    cudaFuncSetAttribute(tc_gemm<2,2,false,false,0>, cudaFuncAttributeMaxDynamicSharedMemorySize, SMEM_WM2);
    cudaFuncSetAttribute(tc_gemm<2,0,false,false,0>, cudaFuncAttributeMaxDynamicSharedMemorySize, SMEM_WM2);
    cudaFuncSetAttribute(tc_gemm<2,0,false,false,1>, cudaFuncAttributeMaxDynamicSharedMemorySize, SMEM_WM2);
    cudaFuncSetAttribute(tc_gemm<2,1,false,false,2>, cudaFuncAttributeMaxDynamicSharedMemorySize, SMEM_WM2);
    cudaFuncSetAttribute(tc_gemm<1,0,true,false,0>, cudaFuncAttributeMaxDynamicSharedMemorySize, SMEM_WM1);
    cudaFuncSetAttribute(tc_gemm<2,1,true,true,0>, cudaFuncAttributeMaxDynamicSharedMemorySize, SMEM_WM2);
    cudaFuncSetAttribute(tc_gemm<2,0,true,false,0>, cudaFuncAttributeMaxDynamicSharedMemorySize, SMEM_WM2);

    const dim3 t8(32, 8);
    // weight transpose -> single fp16
    tsplit_ker<<<dim3(128,16,4), t8>>>(Wq, 4096, 512L*4096, 0, Hp+O_WQ, 512, 4096L*512, 0, 1);
    tsplit_ker<<<dim3(128,16,4), t8>>>(Wk, 4096, 512L*4096, 0, Hp+O_WK, 512, 4096L*512, 0, 1);
    tsplit_ker<<<dim3(128,16,4), t8>>>(Wv, 4096, 512L*4096, 0, Hp+O_WV, 512, 4096L*512, 0, 1);
    tsplit_ker<<<dim3(16,128,4), t8>>>(Wu,  512, 4096L*512, 0, Hp+O_WU, 4096, 512L*4096, 0, 1);
    tsplit_ker<<<dim3(64,16,4),  t8>>>(W1, 2048, 512L*2048, 0, Hp+O_W1, 512, 2048L*512, 0, 1);
    tsplit_ker<<<dim3(16,64,4),  t8>>>(W2,  512, 2048L*512, 0, Hp+O_W2, 2048, 512L*2048, 0, 1);
    tsplit_ker<<<dim3(1000,16,1),t8>>>(uW, 32000, 0, 0, Hp+O_UN, 512, 0, 0, 1);

    embed_ker<<<(BT*512)/256, 256>>>(x, eW, F+F_H, Hp+O_HHI, Hp+O_HLO);

    const float isk = 0.04419417382415922f; // 1/sqrt(512)
    const dim3 gQKV(32,16,1), gATT(4,4,32), gOUT64(4,32,1), gFF(16,16,1);

    for (int i = 0; i < 4; i++) {
        const long w3 = (long)i * 4096 * 512, w12 = (long)i * 2048 * 512;
        // Q (split out), K (single out), V (fp32 out)
        tc_gemm<2,1,false,false,0><<<gQKV,256,SMEM_WM2>>>(Hp+O_HHI, Hp+O_HLO, 512,0,0,
            Hp+O_WQ+w3, 512,0,0, nullptr,
            nullptr, Hp+O_QHI, Hp+O_QLO, 4096,0,0, 512, 1, 1.0f);
        tc_gemm<2,2,false,false,0><<<gQKV,256,SMEM_WM2>>>(Hp+O_HHI, Hp+O_HLO, 512,0,0,
            Hp+O_WK+w3, 512,0,0, nullptr,
            nullptr, Hp+O_K, nullptr, 4096,0,0, 512, 1, 1.0f);
        tc_gemm<2,0,false,false,0><<<gQKV,256,SMEM_WM2>>>(Hp+O_HHI, Hp+O_HLO, 512,0,0,
            Hp+O_WV+w3, 512,0,0, nullptr,
            F+F_V, nullptr, nullptr, 4096,0,0, 512, 1, 1.0f);
        // V^T single fp16 per (b,h): [t,d] -> [d,t]
        tsplit_ker<<<dim3(16,16,32), t8>>>(F+F_V, 4096, 512L*4096, 512,
            Hp+O_VT, 512, 8L*512*512, 512L*512, 8);
        // scores = Q K^T / sqrt(k), causal tile skip; A=Q(split), B=K(single)
        tc_gemm<2,0,false,false,1><<<gATT,256,SMEM_WM2>>>(
            Hp+O_QHI, Hp+O_QLO, 4096, 512L*4096, 512,
            Hp+O_K, 4096, 512L*4096, 512, nullptr,
            F+F_ATT, nullptr, nullptr, 512, 8L*512*512, 512L*512, 512, 8, isk);
        softmax_ker<<<32*512, 256>>>(F+F_ATT, Hp+O_ATHI, Hp+O_ATLO);
        // y = att @ V (K-limit from causality); A=att(split), B=V^T(single)
        tc_gemm<2,1,false,false,2><<<gATT,256,SMEM_WM2>>>(
            Hp+O_ATHI, Hp+O_ATLO, 512, 8L*512*512, 512L*512,
            Hp+O_VT, 512, 8L*512*512, 512L*512, nullptr,
            nullptr, Hp+O_YHI, Hp+O_YLO, 4096, 512L*4096, 512, 512, 8, 1.0f);
        // out proj + bu -> fp32 t1 (64-row tiles)
        tc_gemm<1,0,true,false,0><<<gOUT64,256,SMEM_WM1>>>(Hp+O_YHI, Hp+O_YLO, 4096,0,0,
            Hp+O_WU+w3, 4096,0,0, bu + (long)i*512,
            F+F_T1, nullptr, nullptr, 512,0,0, 4096, 1, 1.0f);
        ln_ker<<<BT,256>>>(F+F_T1, F+F_H, ln1w+(long)i*512, ln1b+(long)i*512,
                           F+F_H, Hp+O_HHI, Hp+O_HLO);
        // FFN up + GELU (split out)
        tc_gemm<2,1,true,true,0><<<gFF,256,SMEM_WM2>>>(Hp+O_HHI, Hp+O_HLO, 512,0,0,
            Hp+O_W1+w12, 512,0,0, b1 + (long)i*2048,
            nullptr, Hp+O_FHI, Hp+O_FLO, 2048,0,0, 512, 1, 1.0f);
        // FFN down + b2 -> fp32 t1 (64-row tiles)
        tc_gemm<1,0,true,false,0><<<gOUT64,256,SMEM_WM1>>>(Hp+O_FHI, Hp+O_FLO, 2048,0,0,
            Hp+O_W2+w12, 2048,0,0, b2 + (long)i*512,
            F+F_T1, nullptr, nullptr, 512,0,0, 2048, 1, 1.0f);
        ln_ker<<<BT,256>>>(F+F_T1, F+F_H, ln2w+(long)i*512, ln2b+(long)i*512,
                           F+F_H, Hp+O_HHI, Hp+O_HLO);
    }
    // final LN (no residual)
    ln_ker<<<BT,256>>>(F+F_H, nullptr, lnfw, lnfb, F+F_T1, Hp+O_HHI, Hp+O_HLO);
    // unembed
    tc_gemm<2,0,true,false,0><<<dim3(250,16,1),256,SMEM_WM2>>>(Hp+O_HHI, Hp+O_HLO, 512,0,0,
        Hp+O_UN, 512,0,0, ub,
        outp, nullptr, nullptr, 32000,0,0, 512, 1, 1.0f);
}

// round 14
// speedup vs baseline: 1.2059x; 1.2059x over previous
#include <cuda_runtime.h>
#include <cuda_bf16.h>
#include <math.h>
#include <stdint.h>

#define TSEQ 512
#define KDIM 512
#define VOCAB 32000
#define BT 2048

// ---------- scratch pools ----------
constexpr long E_H = 2048L*512, E_QK = 2048L*8192, E_QKV = 2048L*4096,
               E_ATT = 32L*512*512, E_FF = 2048L*2048,
               E_WQK = 4L*8192*512, E_W3 = 4L*4096*512, E_W12 = 4L*2048*512,
               E_UN = 32000L*512;
constexpr long O_HHI=0, O_HLO=O_HHI+E_H,
 O_QKHI=O_HLO+E_H, O_QKLO=O_QKHI+E_QK,
 O_VTHI=O_QKLO+E_QK, O_VTLO=O_VTHI+E_ATT,
 O_ATHI=O_VTLO+E_ATT, O_ATLO=O_ATHI+E_ATT,
 O_YHI=O_ATLO+E_ATT, O_YLO=O_YHI+E_QKV,
 O_FHI=O_YLO+E_QKV, O_FLO=O_FHI+E_FF,
 O_WQKHI=O_FLO+E_FF, O_WQKLO=O_WQKHI+E_WQK,
 O_WVHI=O_WQKLO+E_WQK, O_WVLO=O_WVHI+E_W3,
 O_WUHI=O_WVLO+E_W3, O_WULO=O_WUHI+E_W3,
 O_W1HI=O_WULO+E_W3, O_W1LO=O_W1HI+E_W12,
 O_W2HI=O_W1LO+E_W12, O_W2LO=O_W2HI+E_W12,
 O_UNHI=O_W2LO+E_W12, O_UNLO=O_UNHI+E_UN, BF_TOTAL=O_UNLO+E_UN;
__device__ __nv_bfloat16 g_bf[BF_TOTAL];

constexpr long F_H=0, F_V=F_H+E_H, F_ATT=F_V+E_QKV, F_T1=F_ATT+E_ATT,
               F_P=F_T1+E_H, F_TOTAL=F_P+4*E_H;
__device__ float g_f[F_TOTAL];

// ---------- helpers ----------
__device__ __forceinline__ uint32_t s2u(const void* p) {
    uint32_t a;
    asm("{ .reg .u64 t; cvta.to.shared.u64 t, %1; cvt.u32.u64 %0, t; }" : "=r"(a) : "l"(p));
    return a;
}
__device__ __forceinline__ void ldm4(uint32_t& r0, uint32_t& r1, uint32_t& r2, uint32_t& r3,
                                     uint32_t addr) {
    asm volatile("ldmatrix.sync.aligned.m8n8.x4.shared.b16 {%0,%1,%2,%3}, [%4];"
                 : "=r"(r0), "=r"(r1), "=r"(r2), "=r"(r3) : "r"(addr));
}
__device__ __forceinline__ void mma16816(float* c, uint32_t a0, uint32_t a1, uint32_t a2,
                                         uint32_t a3, uint32_t b0, uint32_t b1) {
    asm volatile(
        "mma.sync.aligned.m16n8k16.row.col.f32.bf16.bf16.f32 "
        "{%0,%1,%2,%3}, {%4,%5,%6,%7}, {%8,%9}, {%0,%1,%2,%3};"
        : "+f"(c[0]), "+f"(c[1]), "+f"(c[2]), "+f"(c[3])
        : "r"(a0), "r"(a1), "r"(a2), "r"(a3), "r"(b0), "r"(b1));
}
__device__ __forceinline__ void cpa16(uint32_t dst, const void* src) {
    asm volatile("cp.async.cg.shared.global [%0], [%1], 16;" :: "r"(dst), "l"(src));
}
__device__ __forceinline__ void cpcommit() { asm volatile("cp.async.commit_group;"); }
__device__ __forceinline__ void cpwait0() { asm volatile("cp.async.wait_group 0;"); }
__device__ __forceinline__ void cpwait1() { asm volatile("cp.async.wait_group 1;"); }

__device__ __forceinline__ float gelu_exact(float x) {
    return 0.5f * x * (1.0f + erff(x * 0.70710678118654752f));
}
__device__ __forceinline__ void split_st(float v, __nv_bfloat16* hp, __nv_bfloat16* lp) {
    __nv_bfloat16 h = __float2bfloat16(v);
    *hp = h; *lp = __float2bfloat16(v - __bfloat162float(h));
}
__device__ __forceinline__ uint32_t pack_hi(float a, float b) {
    __nv_bfloat16 h0 = __float2bfloat16(a), h1 = __float2bfloat16(b);
    return (uint32_t)*(uint16_t*)&h0 | ((uint32_t)*(uint16_t*)&h1 << 16);
}
__device__ __forceinline__ uint32_t pack_lo(float a, float b) {
    __nv_bfloat16 h0 = __float2bfloat16(a), h1 = __float2bfloat16(b);
    float r0 = a - __bfloat162float(h0), r1 = b - __bfloat162float(h1);
    __nv_bfloat16 l0 = __float2bfloat16(r0), l1 = __float2bfloat16(r1);
    return (uint32_t)*(uint16_t*)&l0 | ((uint32_t)*(uint16_t*)&l1 << 16);
}
__device__ __forceinline__ float wSum(float v) {
    #pragma unroll
    for (int o = 16; o > 0; o >>= 1) v += __shfl_xor_sync(~0u, v, o);
    return v;
}
__device__ __forceinline__ float wMax(float v) {
    #pragma unroll
    for (int o = 16; o > 0; o >>= 1) v = fmaxf(v, __shfl_xor_sync(~0u, v, o));
    return v;
}

// ---------- split-bf16 HMMA GEMM: C[M,N] = alpha*A[M,K]*B[N,K]^T ----------
// Tile: (WM*64) x 128, 8 warps. WM=2: warp 64x32. WM=1: warp 64x16.
// K-chunk 32, cp.async 2-stage, 80B rows (ldmatrix conflict-free).
// SPLITK>0: blockIdx.z = split index; each split covers Kd/SPLITK and writes
// its own fp32 partial buffer at Cf + z*sCb (A/B batch strides must be 0).
constexpr int ROWB = 80;

template<int WM, bool SPLIT, bool BIAS, bool GELU, int CAUSAL, int SPLITK>
__global__ void __launch_bounds__(256, 2)
tc_gemm(const __nv_bfloat16* __restrict__ Ah, const __nv_bfloat16* __restrict__ Al,
        int lda, long sAb, long sAh,
        const __nv_bfloat16* __restrict__ Bh, const __nv_bfloat16* __restrict__ Bl,
        int ldb, long sBb, long sBh,
        const float* __restrict__ bias,
        float* __restrict__ Cf, __nv_bfloat16* __restrict__ Chi, __nv_bfloat16* __restrict__ Clo,
        int ldc, long sCb, long sCh, int Kd, int Hdiv, float alpha)
{
    constexpr int MT  = WM * 64;
    constexpr int WNW = 8 / WM;
    constexpr int NW  = 128 / WNW;
    constexpr int NFR = NW / 8;
    constexpr int APL = MT * ROWB;
    constexpr int BPL = 128 * ROWB;
    constexpr int STGB = 2 * APL + 2 * BPL;

    const int m0 = blockIdx.y * MT, n0 = blockIdx.x * 128;
    if (CAUSAL == 1 && n0 > m0 + MT - 1) return;

    const int bz = blockIdx.z;
    int bb, hh, kofs, Kloc;
    if (SPLITK > 0) {
        Kloc = Kd / SPLITK; kofs = bz * Kloc; bb = bz; hh = 0;
    } else {
        bb = bz / Hdiv; hh = bz - bb * Hdiv; kofs = 0; Kloc = Kd;
    }
    Ah += (long)bb*sAb + (long)hh*sAh;  Al += (long)bb*sAb + (long)hh*sAh;
    Bh += (long)bb*sBb + (long)hh*sBh;  Bl += (long)bb*sBb + (long)hh*sBh;
    const long coff = (long)bb*sCb + (long)hh*sCh;

    extern __shared__ char smem[];
    const uint32_t sb = s2u(smem);
    const int tid = threadIdx.x, wid = tid >> 5, lane = tid & 31;
    const int wm = wid / WNW, wn = wid % WNW;

    int nk = Kloc >> 5;
    if (CAUSAL == 2) { int kl = m0 + MT; if (kl > Kloc) kl = Kloc; nk = kl >> 5; }

    float acc[4][NFR][4];
    #pragma unroll
    for (int i = 0; i < 4; i++)
        #pragma unroll
        for (int j = 0; j < NFR; j++)
            #pragma unroll
            for (int q = 0; q < 4; q++) acc[i][j][q] = 0.0f;

    auto load_stage = [&](int st, int kt) {
        const int k0 = kofs + (kt << 5);
        const uint32_t base = sb + st * STGB;
        #pragma unroll
        for (int it = 0; it < MT / 32; it++) {
            int id = it * 256 + tid;
            int plane = id / (MT * 4), rem = id % (MT * 4), r = rem >> 2, c = rem & 3;
            const __nv_bfloat16* src = plane ? Al : Ah;
            cpa16(base + plane * APL + r * ROWB + c * 16,
                  src + (long)(m0 + r) * lda + k0 + c * 8);
        }
        #pragma unroll
        for (int it = 0; it < 4; it++) {
            int id = it * 256 + tid;
            int plane = id >> 9, rem = id & 511, r = rem >> 2, c = rem & 3;
            const __nv_bfloat16* src = plane ? Bl : Bh;
            cpa16(base + 2 * APL + plane * BPL + r * ROWB + c * 16,
                  src + (long)(n0 + r) * ldb + k0 + c * 8);
        }
    };

    load_stage(0, 0);
    cpcommit();

    for (int kt = 0; kt < nk; kt++) {
        const int st = kt & 1;
        if (kt + 1 < nk) { load_stage(st ^ 1, kt + 1); cpcommit(); cpwait1(); }
        else cpwait0();
        __syncthreads();

        const uint32_t stg = sb + st * STGB;
        #pragma unroll
        for (int kk = 0; kk < 2; kk++) {
            uint32_t bh[NFR][2], bl[NFR][2];
            {
                const int q = lane >> 3, w8 = lane & 7;
                const uint32_t rofs = (uint32_t)(wn * NW + w8 + ((q >> 1) << 3)) * ROWB
                                    + kk * 32 + ((q & 1) << 4);
                #pragma unroll
                for (int np = 0; np < NFR / 2; np++) {
                    uint32_t bd = stg + 2 * APL + rofs + (uint32_t)(np * 16) * ROWB;
                    uint32_t r0, r1, r2, r3;
                    ldm4(r0, r1, r2, r3, bd);
                    bh[np*2][0] = r0; bh[np*2][1] = r1;
                    bh[np*2+1][0] = r2; bh[np*2+1][1] = r3;
                    ldm4(r0, r1, r2, r3, bd + BPL);
                    bl[np*2][0] = r0; bl[np*2][1] = r1;
                    bl[np*2+1][0] = r2; bl[np*2+1][1] = r3;
                }
            }
            const uint32_t rofsA = (uint32_t)(wm * 64 + (lane & 15)) * ROWB
                                 + kk * 32 + ((lane >> 4) << 4);
            #pragma unroll
            for (int mf = 0; mf < 4; mf++) {
                uint32_t a0, a1, a2, a3, l0, l1, l2, l3;
                uint32_t ad = stg + rofsA + (uint32_t)(mf * 16) * ROWB;
                ldm4(a0, a1, a2, a3, ad);
                ldm4(l0, l1, l2, l3, ad + APL);
                #pragma unroll
                for (int nf = 0; nf < NFR; nf++) {
                    mma16816(acc[mf][nf], a0, a1, a2, a3, bh[nf][0], bh[nf][1]);
                    mma16816(acc[mf][nf], a0, a1, a2, a3, bl[nf][0], bl[nf][1]);
                    mma16816(acc[mf][nf], l0, l1, l2, l3, bh[nf][0], bh[nf][1]);
                }
            }
        }
        __syncthreads();
    }

    // ---- epilogue ----
    const int mbase = m0 + wm * 64 + (lane >> 2);
    const int nbase = n0 + wn * NW + (lane & 3) * 2;
    #pragma unroll
    for (int mf = 0; mf < 4; mf++) {
        #pragma unroll
        for (int nf = 0; nf < NFR; nf++) {
            const int m = mbase + mf * 16, n = nbase + nf * 8;
            float v0 = acc[mf][nf][0] * alpha, v1 = acc[mf][nf][1] * alpha;
            float v2 = acc[mf][nf][2] * alpha, v3 = acc[mf][nf][3] * alpha;
            if (BIAS) {
                float bb0 = bias[n], bb1 = bias[n + 1];
                v0 += bb0; v1 += bb1; v2 += bb0; v3 += bb1;
            }
            if (GELU) {
                v0 = gelu_exact(v0); v1 = gelu_exact(v1);
                v2 = gelu_exact(v2); v3 = gelu_exact(v3);
            }
            const long r0 = coff + (long)m * ldc + n;
            const long r1 = coff + (long)(m + 8) * ldc + n;
            if (!SPLIT) {
                *(float2*)(Cf + r0) = make_float2(v0, v1);
                *(float2*)(Cf + r1) = make_float2(v2, v3);
            } else {
                *(uint32_t*)(Chi + r0) = pack_hi(v0, v1);
                *(uint32_t*)(Clo + r0) = pack_lo(v0, v1);
                *(uint32_t*)(Chi + r1) = pack_hi(v2, v3);
                *(uint32_t*)(Clo + r1) = pack_lo(v2, v3);
            }
        }
    }
}

constexpr int SMEM_WM2 = 2 * (2 * 128 * ROWB + 2 * 128 * ROWB);  // 81920
constexpr int SMEM_WM1 = 2 * (2 * 64 * ROWB + 2 * 128 * ROWB);   // 61440

// ---------- transpose + split: out[C,R] = in[R,C] ----------
__global__ void tsplit_ker(const float* __restrict__ in, int ldin, long sInB, long sInH,
                           __nv_bfloat16* __restrict__ oh, __nv_bfloat16* __restrict__ ol,
                           int ldout, long sOutB, long sOutH, int Hdiv)
{
    __shared__ float t[32][33];
    const int bz = blockIdx.z, bb = bz / Hdiv, hh = bz - bb * Hdiv;
    in += (long)bb*sInB + (long)hh*sInH;
    oh += (long)bb*sOutB + (long)hh*sOutH;
    ol += (long)bb*sOutB + (long)hh*sOutH;
    const int c0 = blockIdx.x * 32, r0 = blockIdx.y * 32;
    const int tx = threadIdx.x, ty = threadIdx.y;
    #pragma unroll
    for (int i = 0; i < 4; i++) {
        int r = ty + i * 8;
        t[r][tx] = in[(long)(r0 + r) * ldin + c0 + tx];
    }
    __syncthreads();
    #pragma unroll
    for (int i = 0; i < 4; i++) {
        int rr = ty + i * 8;
        long o = (long)(c0 + rr) * ldout + r0 + tx;
        split_st(t[tx][rr], oh + o, ol + o);
    }
}

// ---------- embed + positional ----------
__global__ void embed_ker(const int* __restrict__ x, const float* __restrict__ eW,
                          float* __restrict__ h,
                          __nv_bfloat16* __restrict__ hh, __nv_bfloat16* __restrict__ hl)
{
    long i = (long)blockIdx.x * blockDim.x + threadIdx.x;
    int d = (int)(i & 511);
    long bt = i >> 9;
    int t = (int)(bt & 511);
    int tok = x[bt];
    int j = d >> 1;
    float div = powf(10000.0f, (float)j * (1.0f / 128.0f));
    float ang = (float)t / div;
    float p = (d & 1) ? cosf(ang) : sinf(ang);
    float v = eW[(long)tok * 512 + d] + p;
    h[i] = v;
    split_st(v, hh + i, hl + i);
}

// ---------- causal softmax -> split ----------
__global__ void __launch_bounds__(256)
softmax_ker(const float* __restrict__ att,
            __nv_bfloat16* __restrict__ oh, __nv_bfloat16* __restrict__ ol)
{
    __shared__ float red[8];
    const int r = blockIdx.x, q = r & 511, tid = threadIdx.x;
    const float* row = att + (long)r * 512;
    float x0 = (tid       <= q) ? row[tid]       : -3.0e38f;
    float x1 = (tid + 256 <= q) ? row[tid + 256] : -3.0e38f;
    float m = wMax(fmaxf(x0, x1));
    if ((tid & 31) == 0) red[tid >> 5] = m;
    __syncthreads();
    m = red[0];
    #pragma unroll
    for (int i = 1; i < 8; i++) m = fmaxf(m, red[i]);
    __syncthreads();
    float e0 = (tid       <= q) ? expf(x0 - m) : 0.0f;
    float e1 = (tid + 256 <= q) ? expf(x1 - m) : 0.0f;
    float s = wSum(e0 + e1);
    if ((tid & 31) == 0) red[tid >> 5] = s;
    __syncthreads();
    s = red[0];
    #pragma unroll
    for (int i = 1; i < 8; i++) s += red[i];
    float inv = 1.0f / s;
    long base = (long)r * 512;
    split_st(e0 * inv, oh + base + tid,       ol + base + tid);
    split_st(e1 * inv, oh + base + tid + 256, ol + base + tid + 256);
}

// ---------- (residual+) LayerNorm -> fp32 + split ----------
__global__ void __launch_bounds__(256)
ln_ker(const float* __restrict__ in, const float* __restrict__ res,
       const float* __restrict__ w, const float* __restrict__ b,
       float* __restrict__ out, __nv_bfloat16* __restrict__ oh, __nv_bfloat16* __restrict__ ol)
{
    __shared__ float red[8];
    const int r = blockIdx.x, tid = threadIdx.x;
    const long base = (long)r * 512;
    float x0 = in[base + tid], x1 = in[base + tid + 256];
    if (res) { x0 += res[base + tid]; x1 += res[base + tid + 256]; }
    float s = wSum(x0 + x1);
    if ((tid & 31) == 0) red[tid >> 5] = s;
    __syncthreads();
    float tot = red[0];
    #pragma unroll
    for (int i = 1; i < 8; i++) tot += red[i];
    float mean = tot * (1.0f / 512.0f);
    __syncthreads();
    float d0 = x0 - mean, d1 = x1 - mean;
    float s2 = wSum(d0 * d0 + d1 * d1);
    if ((tid & 31) == 0) red[tid >> 5] = s2;
    __syncthreads();
    float v = red[0];
    #pragma unroll
    for (int i = 1; i < 8; i++) v += red[i];
    float inv = 1.0f / sqrtf(v * (1.0f / 512.0f) + 1e-5f);
    float y0 = d0 * inv * w[tid]       + b[tid];
    float y1 = d1 * inv * w[tid + 256] + b[tid + 256];
    out[base + tid] = y0; out[base + tid + 256] = y1;
    split_st(y0, oh + base + tid,       ol + base + tid);
    split_st(y1, oh + base + tid + 256, ol + base + tid + 256);
}

// ---------- LN over sum of 4 split-K partials + bias + residual ----------
__global__ void __launch_bounds__(256)
ln4_ker(const float* __restrict__ parts, const float* __restrict__ gb,
        const float* __restrict__ res,
        const float* __restrict__ w, const float* __restrict__ b,
        float* __restrict__ out, __nv_bfloat16* __restrict__ oh, __nv_bfloat16* __restrict__ ol)
{
    __shared__ float red[8];
    const int r = blockIdx.x, tid = threadIdx.x;
    const long base = (long)r * 512;
    constexpr long S = 2048L * 512;
    float x0 = parts[base + tid]         + parts[S + base + tid]
             + parts[2*S + base + tid]   + parts[3*S + base + tid]
             + gb[tid] + res[base + tid];
    float x1 = parts[base + tid + 256]       + parts[S + base + tid + 256]
             + parts[2*S + base + tid + 256] + parts[3*S + base + tid + 256]
             + gb[tid + 256] + res[base + tid + 256];
    float s = wSum(x0 + x1);
    if ((tid & 31) == 0) red[tid >> 5] = s;
    __syncthreads();
    float tot = red[0];
    #pragma unroll
    for (int i = 1; i < 8; i++) tot += red[i];
    float mean = tot * (1.0f / 512.0f);
    __syncthreads();
    float d0 = x0 - mean, d1 = x1 - mean;
    float s2 = wSum(d0 * d0 + d1 * d1);
    if ((tid & 31) == 0) red[tid >> 5] = s2;
    __syncthreads();
    float v = red[0];
    #pragma unroll
    for (int i = 1; i < 8; i++) v += red[i];
    float inv = 1.0f / sqrtf(v * (1.0f / 512.0f) + 1e-5f);
    float y0 = d0 * inv * w[tid]       + b[tid];
    float y1 = d1 * inv * w[tid + 256] + b[tid + 256];
    out[base + tid] = y0; out[base + tid + 256] = y1;
    split_st(y0, oh + base + tid,       ol + base + tid);
    split_st(y1, oh + base + tid + 256, ol + base + tid + 256);
}

// ---------- launch ----------
extern "C" void kernel_launch(void* const* d_in, const int* in_sizes, int n_in,
                              void* d_out, int out_size)
{
    (void)in_sizes; (void)n_in; (void)out_size;
    const int*   x    = (const int*)  d_in[0];
    const float* eW   = (const float*)d_in[1];
    const float* Wq   = (const float*)d_in[2];
    const float* Wk   = (const float*)d_in[3];
    const float* Wv   = (const float*)d_in[4];
    const float* Wu   = (const float*)d_in[5];
    const float* bu   = (const float*)d_in[6];
    const float* W1   = (const float*)d_in[7];
    const float* b1   = (const float*)d_in[8];
    const float* W2   = (const float*)d_in[9];
    const float* b2   = (const float*)d_in[10];
    const float* ln1w = (const float*)d_in[11];
    const float* ln1b = (const float*)d_in[12];
    const float* ln2w = (const float*)d_in[13];
    const float* ln2b = (const float*)d_in[14];
    const float* lnfw = (const float*)d_in[15];
    const float* lnfb = (const float*)d_in[16];
    const float* uW   = (const float*)d_in[17];
    const float* ub   = (const float*)d_in[18];
    float* outp = (float*)d_out;

    void *pb = nullptr, *pf = nullptr;
    cudaGetSymbolAddress(&pb, g_bf);
    cudaGetSymbolAddress(&pf, g_f);
    __nv_bfloat16* B = (__nv_bfloat16*)pb;
    float* F = (float*)pf;

    cudaFuncSetAttribute(tc_gemm<2,true,false,false,0,0>, cudaFuncAttributeMaxDynamicSharedMemorySize, SMEM_WM2);
    cudaFuncSetAttribute(tc_gemm<2,false,false,false,0,0>, cudaFuncAttributeMaxDynamicSharedMemorySize, SMEM_WM2);
    cudaFuncSetAttribute(tc_gemm<2,false,false,false,1,0>, cudaFuncAttributeMaxDynamicSharedMemorySize, SMEM_WM2);
    cudaFuncSetAttribute(tc_gemm<2,true,false,false,2,0>, cudaFuncAttributeMaxDynamicSharedMemorySize, SMEM_WM2);
    cudaFuncSetAttribute(tc_gemm<1,false,false,false,0,4>, cudaFuncAttributeMaxDynamicSharedMemorySize, SMEM_WM1);
    cudaFuncSetAttribute(tc_gemm<2,true,true,true,0,0>, cudaFuncAttributeMaxDynamicSharedMemorySize, SMEM_WM2);
    cudaFuncSetAttribute(tc_gemm<2,false,true,false,0,0>, cudaFuncAttributeMaxDynamicSharedMemorySize, SMEM_WM2);

    const dim3 t8(32, 8);
    // weight transpose+split: Wq/Wk into fused per-block [8192,512] sections
    tsplit_ker<<<dim3(128,16,4), t8>>>(Wq, 4096, 512L*4096, 0,
        B+O_WQKHI, B+O_WQKLO, 512, 8192L*512, 0, 1);
    tsplit_ker<<<dim3(128,16,4), t8>>>(Wk, 4096, 512L*4096, 0,
        B+O_WQKHI+4096L*512, B+O_WQKLO+4096L*512, 512, 8192L*512, 0, 1);
    tsplit_ker<<<dim3(128,16,4), t8>>>(Wv, 4096, 512L*4096, 0, B+O_WVHI, B+O_WVLO, 512, 4096L*512, 0, 1);
    tsplit_ker<<<dim3(16,128,4), t8>>>(Wu,  512, 4096L*512, 0, B+O_WUHI, B+O_WULO, 4096, 512L*4096, 0, 1);
    tsplit_ker<<<dim3(64,16,4),  t8>>>(W1, 2048, 512L*2048, 0, B+O_W1HI, B+O_W1LO, 512, 2048L*512, 0, 1);
    tsplit_ker<<<dim3(16,64,4),  t8>>>(W2,  512, 2048L*512, 0, B+O_W2HI, B+O_W2LO, 2048, 512L*2048, 0, 1);
    tsplit_ker<<<dim3(1000,16,1),t8>>>(uW, 32000, 0, 0, B+O_UNHI, B+O_UNLO, 512, 0, 0, 1);

    embed_ker<<<(BT*512)/256, 256>>>(x, eW, F+F_H, B+O_HHI, B+O_HLO);

    const float isk = 0.04419417382415922f; // 1/sqrt(512)
    const dim3 gQK(64,16,1), gV(32,16,1), gATT(4,4,32), gSK(4,32,4), gFF(16,16,1);

    for (int i = 0; i < 4; i++) {
        const long wqk = (long)i * 8192 * 512;
        const long w3 = (long)i * 4096 * 512, w12 = (long)i * 2048 * 512;
        // Q+K fused projection (split out to [2048,8192])
        tc_gemm<2,true,false,false,0,0><<<gQK,256,SMEM_WM2>>>(B+O_HHI, B+O_HLO, 512,0,0,
            B+O_WQKHI+wqk, B+O_WQKLO+wqk, 512,0,0, nullptr,
            nullptr, B+O_QKHI, B+O_QKLO, 8192,0,0, 512, 1, 1.0f);
        // V (fp32 out)
        tc_gemm<2,false,false,false,0,0><<<gV,256,SMEM_WM2>>>(B+O_HHI, B+O_HLO, 512,0,0,
            B+O_WVHI+w3, B+O_WVLO+w3, 512,0,0, nullptr,
            F+F_V, nullptr, nullptr, 4096,0,0, 512, 1, 1.0f);
        // V^T split per (b,h): [t,d] -> [d,t]
        tsplit_ker<<<dim3(16,16,32), t8>>>(F+F_V, 4096, 512L*4096, 512,
            B+O_VTHI, B+O_VTLO, 512, 8L*512*512, 512L*512, 8);
        // scores = Q K^T / sqrt(k), causal tile skip; Q at col 0, K at col 4096
        tc_gemm<2,false,false,false,1,0><<<gATT,256,SMEM_WM2>>>(
            B+O_QKHI, B+O_QKLO, 8192, 512L*8192, 512,
            B+O_QKHI+4096, B+O_QKLO+4096, 8192, 512L*8192, 512, nullptr,
            F+F_ATT, nullptr, nullptr, 512, 8L*512*512, 512L*512, 512, 8, isk);
        softmax_ker<<<32*512, 256>>>(F+F_ATT, B+O_ATHI, B+O_ATLO);
        // y = att @ V (K-limit from causality)
        tc_gemm<2,true,false,false,2,0><<<gATT,256,SMEM_WM2>>>(
            B+O_ATHI, B+O_ATLO, 512, 8L*512*512, 512L*512,
            B+O_VTHI, B+O_VTLO, 512, 8L*512*512, 512L*512, nullptr,
            nullptr, B+O_YHI, B+O_YLO, 4096, 512L*4096, 512, 512, 8, 1.0f);
        // out proj, split-K x4 -> 4 fp32 partials (bias added in ln4)
        tc_gemm<1,false,false,false,0,4><<<gSK,256,SMEM_WM1>>>(B+O_YHI, B+O_YLO, 4096,0,0,
            B+O_WUHI+w3, B+O_WULO+w3, 4096,0,0, nullptr,
            F+F_P, nullptr, nullptr, 512, 2048L*512, 0, 4096, 1, 1.0f);
        ln4_ker<<<BT,256>>>(F+F_P, bu+(long)i*512, F+F_H,
                            ln1w+(long)i*512, ln1b+(long)i*512,
                            F+F_H, B+O_HHI, B+O_HLO);
        // FFN up + GELU (split out)
        tc_gemm<2,true,true,true,0,0><<<gFF,256,SMEM_WM2>>>(B+O_HHI, B+O_HLO, 512,0,0,
            B+O_W1HI+w12, B+O_W1LO+w12, 512,0,0, b1 + (long)i*2048,
            nullptr, B+O_FHI, B+O_FLO, 2048,0,0, 512, 1, 1.0f);
        // FFN down, split-K x4 -> partials (bias in ln4)
        tc_gemm<1,false,false,false,0,4><<<gSK,256,SMEM_WM1>>>(B+O_FHI, B+O_FLO, 2048,0,0,
            B+O_W2HI+w12, B+O_W2LO+w12, 2048,0,0, nullptr,
            F+F_P, nullptr, nullptr, 512, 2048L*512, 0, 2048, 1, 1.0f);
        ln4_ker<<<BT,256>>>(F+F_P, b2+(long)i*512, F+F_H,
                            ln2w+(long)i*512, ln2b+(long)i*512,
                            F+F_H, B+O_HHI, B+O_HLO);
    }
    // final LN (no residual)
    ln_ker<<<BT,256>>>(F+F_H, nullptr, lnfw, lnfb, F+F_T1, B+O_HHI, B+O_HLO);
    // unembed
    tc_gemm<2,false,true,false,0,0><<<dim3(250,16,1),256,SMEM_WM2>>>(B+O_HHI, B+O_HLO, 512,0,0,
        B+O_UNHI, B+O_UNLO, 512,0,0, ub,
        outp, nullptr, nullptr, 32000,0,0, 512, 1, 1.0f);
}